// round 6
// baseline (speedup 1.0000x reference)
#include <cuda_runtime.h>
#include <math.h>

// Flow_49546742727298: CNF Euler, exact divergence via analytic trace.
// R6: fix wave quantization — 64-thread CTAs, grid=1024 (6.92 CTAs/SM, 98.8%
//     balance) vs grid=256 (1.73/SM, 86.5%). Instruction mix as R5 minus the
//     wasted p1 zero-seed fma.

#define THREADS 64
#define MSAMP   2
#define NSTEPS  2
#define ROWF    36

typedef unsigned long long u64;

__device__ __forceinline__ u64 fma2(u64 a, u64 b, u64 c) {
    u64 d; asm("fma.rn.f32x2 %0, %1, %2, %3;" : "=l"(d) : "l"(a), "l"(b), "l"(c)); return d;
}
__device__ __forceinline__ u64 mul2(u64 a, u64 b) {
    u64 d; asm("mul.rn.f32x2 %0, %1, %2;" : "=l"(d) : "l"(a), "l"(b)); return d;
}
__device__ __forceinline__ u64 add2(u64 a, u64 b) {
    u64 d; asm("add.rn.f32x2 %0, %1, %2;" : "=l"(d) : "l"(a), "l"(b)); return d;
}
__device__ __forceinline__ u64 pack2(float lo, float hi) {
    u64 d; asm("mov.b64 %0, {%1, %2};" : "=l"(d) : "f"(lo), "f"(hi)); return d;
}
__device__ __forceinline__ void unpack2(u64 p, float& lo, float& hi) {
    asm("mov.b64 {%0, %1}, %2;" : "=f"(lo), "=f"(hi) : "l"(p));
}
__device__ __forceinline__ float fast_tanh(float x) {
    float y; asm("tanh.approx.f32 %0, %1;" : "=f"(y) : "f"(x)); return y;
}

// Shared row j (36 floats, 144B):
//  [0..15]  W1[0..15][j]   (i-pairs consecutive -> u64 f32x2 operands)
//  [16] bse0 = b1[j]            [17] bse1 = b1[j]+0.5*wt[j]
//  [18] c[j] = sum_i W1[i][j]*W2[j][i]   [19] pad
//  [20..35] W2[j][0..15]

__global__ void __launch_bounds__(THREADS, 8)
flow_kernel(const float* __restrict__ x0,
            const float* __restrict__ W1,
            const float* __restrict__ b1,
            const float* __restrict__ W2,
            const float* __restrict__ b2,
            float* __restrict__ out,
            int batch)
{
    __shared__ __align__(16) float sp[64 * ROWF];
    __shared__ __align__(16) float sb2[16];
    __shared__ float s_csum;

    const int tid = threadIdx.x;

    // 64 threads -> exactly one weight row each.
    {
        const int j = tid;
        float* row = &sp[j * ROWF];
        float c = 0.f;
        #pragma unroll
        for (int i = 0; i < 16; i++) {
            float w1 = W1[i * 64 + j];
            float w2 = W2[j * 16 + i];
            row[i]      = w1;
            row[20 + i] = w2;
            c += w1 * w2;
        }
        float wt = W1[16 * 64 + j];
        float bb = b1[j];
        row[16] = bb;
        row[17] = fmaf(0.5f, wt, bb);
        row[18] = c;
        row[19] = 0.f;
    }
    if (tid < 16) sb2[tid] = b2[tid];
    __syncthreads();
    if (tid == 0) {
        float cs = 0.f;
        #pragma unroll
        for (int j = 0; j < 64; j++) cs += sp[j * ROWF + 18];
        s_csum = cs;
    }
    __syncthreads();
    const float csum = s_csum;

    const int base = blockIdx.x * (THREADS * MSAMP);
    int bs[MSAMP];
    bs[0] = base + tid;
    bs[1] = base + THREADS + tid;
    if (bs[0] >= batch) return;
    const bool has1 = (bs[1] < batch);

    u64 X[MSAMP][8];
    const ulonglong2* xin = (const ulonglong2*)x0;
    #pragma unroll
    for (int m = 0; m < MSAMP; m++) {
        int b = (m == 0 || has1) ? bs[m] : bs[0];
        #pragma unroll
        for (int q = 0; q < 4; q++) {
            ulonglong2 t2 = xin[(size_t)b * 4 + q];
            X[m][2 * q]     = t2.x;
            X[m][2 * q + 1] = t2.y;
        }
    }

    const float dt = 0.5f;
    const u64 dt2 = pack2(dt, dt);
    float logq[MSAMP] = {0.f, 0.f};
    const u64* sb2u = (const u64*)sb2;

    #pragma unroll
    for (int s = 0; s < NSTEPS; s++) {
        u64 V[MSAMP][8];
        #pragma unroll
        for (int m = 0; m < MSAMP; m++)
            #pragma unroll
            for (int k = 0; k < 8; k++) V[m][k] = sb2u[k];
        float hc[MSAMP] = {0.f, 0.f};

        #pragma unroll 4
        for (int j = 0; j < 64; j++) {
            const ulonglong2* rp = (const ulonglong2*)&sp[j * ROWF];
            ulonglong2 wa = rp[0];
            ulonglong2 wb = rp[1];
            ulonglong2 wc = rp[2];
            ulonglong2 wd = rp[3];
            float4 aux = ((const float4*)rp)[4];   // bse0, bse1, c, pad
            ulonglong2 va = rp[5];
            ulonglong2 vb = rp[6];
            ulonglong2 vc = rp[7];
            ulonglong2 vd = rp[8];

            const float bse = (s == 0) ? aux.x : aux.y;
            const u64 bse2 = pack2(bse, 0.f);   // seed for p0 chain

            #pragma unroll
            for (int m = 0; m < MSAMP; m++) {
                u64 p0 = fma2(X[m][0], wa.x, bse2);
                u64 p1 = mul2(X[m][1], wa.y);
                p0 = fma2(X[m][2], wb.x, p0);
                p1 = fma2(X[m][3], wb.y, p1);
                p0 = fma2(X[m][4], wc.x, p0);
                p1 = fma2(X[m][5], wc.y, p1);
                p0 = fma2(X[m][6], wd.x, p0);
                p1 = fma2(X[m][7], wd.y, p1);
                u64 p = add2(p0, p1);
                float lo, hi; unpack2(p, lo, hi);
                float pre = lo + hi;
                float h = fast_tanh(pre);
                hc[m] = fmaf(h * h, aux.z, hc[m]);
                u64 h2 = pack2(h, h);
                V[m][0] = fma2(h2, va.x, V[m][0]);
                V[m][1] = fma2(h2, va.y, V[m][1]);
                V[m][2] = fma2(h2, vb.x, V[m][2]);
                V[m][3] = fma2(h2, vb.y, V[m][3]);
                V[m][4] = fma2(h2, vc.x, V[m][4]);
                V[m][5] = fma2(h2, vc.y, V[m][5]);
                V[m][6] = fma2(h2, vd.x, V[m][6]);
                V[m][7] = fma2(h2, vd.y, V[m][7]);
            }
        }

        #pragma unroll
        for (int m = 0; m < MSAMP; m++) {
            #pragma unroll
            for (int k = 0; k < 8; k++) X[m][k] = fma2(dt2, V[m][k], X[m][k]);
            logq[m] -= dt * (csum - hc[m]);
        }
    }

    ulonglong2* outp = (ulonglong2*)out;
    #pragma unroll
    for (int m = 0; m < MSAMP; m++) {
        if (m == 1 && !has1) break;
        const int b = bs[m];
        #pragma unroll
        for (int q = 0; q < 4; q++) {
            ulonglong2 t2;
            t2.x = X[m][2 * q];
            t2.y = X[m][2 * q + 1];
            outp[(size_t)b * 4 + q] = t2;
        }
        out[(size_t)batch * 16 + b] = logq[m];
    }
}

extern "C" void kernel_launch(void* const* d_in, const int* in_sizes, int n_in,
                              void* d_out, int out_size) {
    const float* x0 = (const float*)d_in[0];
    const float* W1 = (const float*)d_in[1];
    const float* b1 = (const float*)d_in[2];
    const float* W2 = (const float*)d_in[3];
    const float* b2 = (const float*)d_in[4];
    float* out = (float*)d_out;

    const int batch = in_sizes[0] / 16;
    const int per_block = THREADS * MSAMP;
    const int blocks = (batch + per_block - 1) / per_block;
    flow_kernel<<<blocks, THREADS>>>(x0, W1, b1, W2, b2, out, batch);
}

// round 8
// speedup vs baseline: 1.0090x; 1.0090x over previous
#include <cuda_runtime.h>
#include <math.h>

// Flow_49546742727298: CNF Euler, exact divergence via analytic trace.
// R8: R7 (weights in __constant__) with the symbol-address bug fixed:
//     source pointer for the D2D memcpy now comes from cudaGetSymbolAddress.

#define THREADS 128
#define MSAMP   2
#define NSTEPS  2

typedef unsigned long long u64;

// Constant layout, u64 granularity, per hidden unit j (18 u64 = 144B):
//  [0..7]   W1 i-pairs (i=0..15 packed f32x2)
//  [8]      (bse0, bse1) = (b1[j], b1[j]+0.5*wt[j])
//  [9]      (c[j], 0)
//  [10..17] W2 pairs
// Then [1152..1159] = b2 pairs, [1160] = (csum, 0).
#define ROWU 18
#define CPACK_U64 (64 * ROWU + 8 + 1)

__constant__ u64 c_pack[CPACK_U64];
__device__   u64 g_pack[CPACK_U64];

__device__ __forceinline__ u64 fma2(u64 a, u64 b, u64 c) {
    u64 d; asm("fma.rn.f32x2 %0, %1, %2, %3;" : "=l"(d) : "l"(a), "l"(b), "l"(c)); return d;
}
__device__ __forceinline__ u64 mul2(u64 a, u64 b) {
    u64 d; asm("mul.rn.f32x2 %0, %1, %2;" : "=l"(d) : "l"(a), "l"(b)); return d;
}
__device__ __forceinline__ u64 add2(u64 a, u64 b) {
    u64 d; asm("add.rn.f32x2 %0, %1, %2;" : "=l"(d) : "l"(a), "l"(b)); return d;
}
__device__ __forceinline__ u64 pack2(float lo, float hi) {
    u64 d; asm("mov.b64 %0, {%1, %2};" : "=l"(d) : "f"(lo), "f"(hi)); return d;
}
__device__ __forceinline__ void unpack2(u64 p, float& lo, float& hi) {
    asm("mov.b64 {%0, %1}, %2;" : "=f"(lo), "=f"(hi) : "l"(p));
}
__device__ __forceinline__ float fast_tanh(float x) {
    float y; asm("tanh.approx.f32 %0, %1;" : "=f"(y) : "f"(x)); return y;
}

// ---------- prep: pack weights into g_pack ----------
__global__ void prep_kernel(const float* __restrict__ W1,
                            const float* __restrict__ b1,
                            const float* __restrict__ W2,
                            const float* __restrict__ b2)
{
    const int j = threadIdx.x;   // 64 threads
    if (j < 64) {
        float w1v[16], w2v[16];
        float c = 0.f;
        #pragma unroll
        for (int i = 0; i < 16; i++) {
            w1v[i] = W1[i * 64 + j];
            w2v[i] = W2[j * 16 + i];
            c += w1v[i] * w2v[i];
        }
        u64* row = &g_pack[j * ROWU];
        #pragma unroll
        for (int k = 0; k < 8; k++) {
            row[k]      = pack2(w1v[2 * k], w1v[2 * k + 1]);
            row[10 + k] = pack2(w2v[2 * k], w2v[2 * k + 1]);
        }
        float wt = W1[16 * 64 + j];
        float bb = b1[j];
        row[8] = pack2(bb, fmaf(0.5f, wt, bb));
        row[9] = pack2(c, 0.f);
    }
    __syncthreads();
    if (j < 8) {
        g_pack[64 * ROWU + j] = pack2(b2[2 * j], b2[2 * j + 1]);
    }
    if (j == 0) {
        float cs = 0.f;
        for (int k = 0; k < 64; k++) {
            float c, z; unpack2(g_pack[k * ROWU + 9], c, z);
            cs += c;
        }
        g_pack[64 * ROWU + 8] = pack2(cs, 0.f);
    }
}

// ---------- main ----------
__global__ void __launch_bounds__(THREADS, 5)
flow_kernel(const float* __restrict__ x0,
            float* __restrict__ out,
            int batch)
{
    const int tid = threadIdx.x;
    const int base = blockIdx.x * (THREADS * MSAMP);
    int bs[MSAMP];
    bs[0] = base + tid;
    bs[1] = base + THREADS + tid;
    if (bs[0] >= batch) return;
    const bool has1 = (bs[1] < batch);

    u64 X[MSAMP][8];
    const ulonglong2* xin = (const ulonglong2*)x0;
    #pragma unroll
    for (int m = 0; m < MSAMP; m++) {
        int b = (m == 0 || has1) ? bs[m] : bs[0];
        #pragma unroll
        for (int q = 0; q < 4; q++) {
            ulonglong2 t2 = xin[(size_t)b * 4 + q];
            X[m][2 * q]     = t2.x;
            X[m][2 * q + 1] = t2.y;
        }
    }

    float csum, czz;
    unpack2(c_pack[64 * ROWU + 8], csum, czz);

    const float dt = 0.5f;
    const u64 dt2 = pack2(dt, dt);
    float logq[MSAMP] = {0.f, 0.f};

    #pragma unroll
    for (int s = 0; s < NSTEPS; s++) {
        u64 V[MSAMP][8];
        #pragma unroll
        for (int m = 0; m < MSAMP; m++)
            #pragma unroll
            for (int k = 0; k < 8; k++) V[m][k] = c_pack[64 * ROWU + k];
        float hc[MSAMP] = {0.f, 0.f};

        #pragma unroll 4
        for (int j = 0; j < 64; j++) {
            const u64* row = &c_pack[j * ROWU];
            float bse0, bse1; unpack2(row[8], bse0, bse1);
            float cj, cz;     unpack2(row[9], cj, cz);
            const float bse = (s == 0) ? bse0 : bse1;
            const u64 bse2 = pack2(bse, 0.f);

            #pragma unroll
            for (int m = 0; m < MSAMP; m++) {
                u64 p0 = fma2(X[m][0], row[0], bse2);
                u64 p1 = mul2(X[m][1], row[1]);
                p0 = fma2(X[m][2], row[2], p0);
                p1 = fma2(X[m][3], row[3], p1);
                p0 = fma2(X[m][4], row[4], p0);
                p1 = fma2(X[m][5], row[5], p1);
                p0 = fma2(X[m][6], row[6], p0);
                p1 = fma2(X[m][7], row[7], p1);
                u64 p = add2(p0, p1);
                float lo, hi; unpack2(p, lo, hi);
                float pre = lo + hi;
                float h = fast_tanh(pre);
                hc[m] = fmaf(h * h, cj, hc[m]);
                u64 h2 = pack2(h, h);
                V[m][0] = fma2(h2, row[10], V[m][0]);
                V[m][1] = fma2(h2, row[11], V[m][1]);
                V[m][2] = fma2(h2, row[12], V[m][2]);
                V[m][3] = fma2(h2, row[13], V[m][3]);
                V[m][4] = fma2(h2, row[14], V[m][4]);
                V[m][5] = fma2(h2, row[15], V[m][5]);
                V[m][6] = fma2(h2, row[16], V[m][6]);
                V[m][7] = fma2(h2, row[17], V[m][7]);
            }
        }

        #pragma unroll
        for (int m = 0; m < MSAMP; m++) {
            #pragma unroll
            for (int k = 0; k < 8; k++) X[m][k] = fma2(dt2, V[m][k], X[m][k]);
            logq[m] -= dt * (csum - hc[m]);
        }
    }

    ulonglong2* outp = (ulonglong2*)out;
    #pragma unroll
    for (int m = 0; m < MSAMP; m++) {
        if (m == 1 && !has1) break;
        const int b = bs[m];
        #pragma unroll
        for (int q = 0; q < 4; q++) {
            ulonglong2 t2;
            t2.x = X[m][2 * q];
            t2.y = X[m][2 * q + 1];
            outp[(size_t)b * 4 + q] = t2;
        }
        out[(size_t)batch * 16 + b] = logq[m];
    }
}

extern "C" void kernel_launch(void* const* d_in, const int* in_sizes, int n_in,
                              void* d_out, int out_size) {
    const float* x0 = (const float*)d_in[0];
    const float* W1 = (const float*)d_in[1];
    const float* b1 = (const float*)d_in[2];
    const float* W2 = (const float*)d_in[3];
    const float* b2 = (const float*)d_in[4];
    float* out = (float*)d_out;

    const int batch = in_sizes[0] / 16;

    prep_kernel<<<1, 64>>>(W1, b1, W2, b2);

    // Resolve the REAL device address of g_pack (the symbol name itself is a
    // host-side shadow and not a valid device pointer — R7's bug).
    void* gptr = nullptr;
    cudaGetSymbolAddress(&gptr, g_pack);
    cudaMemcpyToSymbolAsync(c_pack, gptr, sizeof(u64) * CPACK_U64, 0,
                            cudaMemcpyDeviceToDevice);

    const int per_block = THREADS * MSAMP;
    const int blocks = (batch + per_block - 1) / per_block;
    flow_kernel<<<blocks, THREADS>>>(x0, out, batch);
}

// round 9
// speedup vs baseline: 1.3690x; 1.3567x over previous
#include <cuda_runtime.h>
#include <math.h>
#include <stdint.h>

// Flow_49546742727298: CNF Euler, exact divergence via analytic trace.
// R9: tf32 tensor cores (mma.sync.m16n8k8). One warp = 16 samples.
//   GEMM1: h_pre[16x64] = x[16x16] @ W1[16x64], bias(b1 + t*wt) folded into C init.
//   tanh in-register (MUFU), div = csum - sum_j h^2 c_j (shuffle-reduced).
//   GEMM2: v[16x16] = h[16x64] @ W2[64x16] + b2.
//   x kept exact fp32; operands pass through cvt.rna.tf32 only at MMA input.
//   Per-warp SMEM buffer for C->A fragment relayout; __syncwarp only.

#define THREADS 128        // 4 warps per CTA, 64 samples per CTA
#define NSTEPS  2
#define BUFW    68         // smem row stride (floats) for 16x64 tile

__device__ float g_c[65];  // c_j (64) + csum

__device__ __forceinline__ uint32_t tf32(float f) {
    uint32_t r; asm("cvt.rna.tf32.f32 %0, %1;" : "=r"(r) : "f"(f)); return r;
}
__device__ __forceinline__ float fast_tanh(float x) {
    float y; asm("tanh.approx.f32 %0, %1;" : "=f"(y) : "f"(x)); return y;
}
__device__ __forceinline__ void mma_tf32(float c[4], const uint32_t a[4],
                                         const uint32_t b0, const uint32_t b1) {
    asm("mma.sync.aligned.m16n8k8.row.col.f32.tf32.tf32.f32 "
        "{%0,%1,%2,%3}, {%4,%5,%6,%7}, {%8,%9}, {%0,%1,%2,%3};"
        : "+f"(c[0]), "+f"(c[1]), "+f"(c[2]), "+f"(c[3])
        : "r"(a[0]), "r"(a[1]), "r"(a[2]), "r"(a[3]), "r"(b0), "r"(b1));
}

// ---------- prep: c_j = sum_i W1[i][j]*W2[j][i], csum ----------
__global__ void prep_kernel(const float* __restrict__ W1,
                            const float* __restrict__ W2)
{
    const int j = threadIdx.x;   // 64
    float c = 0.f;
    #pragma unroll
    for (int i = 0; i < 16; i++)
        c += W1[i * 64 + j] * W2[j * 16 + i];
    g_c[j] = c;
    __syncthreads();
    if (j == 0) {
        float cs = 0.f;
        for (int k = 0; k < 64; k++) cs += g_c[k];
        g_c[64] = cs;
    }
}

// ---------- main ----------
__global__ void __launch_bounds__(THREADS, 2)
flow_kernel(const float* __restrict__ x0,
            const float* __restrict__ W1,
            const float* __restrict__ b1,
            const float* __restrict__ W2,
            const float* __restrict__ b2,
            float* __restrict__ out,
            int batch)
{
    __shared__ float hbuf[4][16 * BUFW];

    const int tid  = threadIdx.x;
    const int lane = tid & 31;
    const int warp = tid >> 5;
    const int g    = lane >> 2;   // group id (row within 8)
    const int tg   = lane & 3;    // thread in group
    const int row0 = blockIdx.x * 64 + warp * 16;   // first sample of this warp
    if (row0 >= batch) return;
    float* buf = hbuf[warp];

    // ---- persistent weight fragments ----
    // W1 B-frags: (k,n) col-major per (nt, kt): b0=(tg, g), b1=(tg+4, g)
    uint32_t w1f[8][2][2];
    #pragma unroll
    for (int nt = 0; nt < 8; nt++)
        #pragma unroll
        for (int kt = 0; kt < 2; kt++) {
            w1f[nt][kt][0] = tf32(W1[(8 * kt + tg)     * 64 + 8 * nt + g]);
            w1f[nt][kt][1] = tf32(W1[(8 * kt + tg + 4) * 64 + 8 * nt + g]);
        }
    // W2 B-frags
    uint32_t w2f[8][2][2];
    #pragma unroll
    for (int kt = 0; kt < 8; kt++)
        #pragma unroll
        for (int nt = 0; nt < 2; nt++) {
            w2f[kt][nt][0] = tf32(W2[(8 * kt + tg)     * 16 + 8 * nt + g]);
            w2f[kt][nt][1] = tf32(W2[(8 * kt + tg + 4) * 16 + 8 * nt + g]);
        }
    // bias / divergence constants at this thread's C columns (2tg, 2tg+1 per nt)
    float bse0[8][2], bse1[8][2], cj[8][2];
    #pragma unroll
    for (int nt = 0; nt < 8; nt++)
        #pragma unroll
        for (int o = 0; o < 2; o++) {
            int col = 8 * nt + 2 * tg + o;
            float bb = b1[col];
            float wt = W1[16 * 64 + col];
            bse0[nt][o] = bb;                    // t = 0
            bse1[nt][o] = fmaf(0.5f, wt, bb);    // t = 0.5
            cj[nt][o]   = g_c[col];
        }
    float b2f[2][2];
    #pragma unroll
    for (int nt = 0; nt < 2; nt++)
        #pragma unroll
        for (int o = 0; o < 2; o++)
            b2f[nt][o] = b2[8 * nt + 2 * tg + o];
    const float csum = g_c[64];

    // ---- x A-fragments, exact fp32: (g,tg),(g+8,tg),(g,tg+4),(g+8,tg+4) per kt ----
    float xe[2][4];
    #pragma unroll
    for (int kt = 0; kt < 2; kt++) {
        xe[kt][0] = x0[(size_t)(row0 + g)     * 16 + 8 * kt + tg];
        xe[kt][1] = x0[(size_t)(row0 + g + 8) * 16 + 8 * kt + tg];
        xe[kt][2] = x0[(size_t)(row0 + g)     * 16 + 8 * kt + tg + 4];
        xe[kt][3] = x0[(size_t)(row0 + g + 8) * 16 + 8 * kt + tg + 4];
    }

    const float dt = 0.5f;
    float logq0 = 0.f, logq1 = 0.f;

    #pragma unroll
    for (int s = 0; s < NSTEPS; s++) {
        // tf32 copies of x for MMA input
        uint32_t xa[2][4];
        #pragma unroll
        for (int kt = 0; kt < 2; kt++)
            #pragma unroll
            for (int i = 0; i < 4; i++)
                xa[kt][i] = tf32(xe[kt][i]);

        // ---- GEMM1: h_pre = x @ W1 + bse ----
        float h[8][4];
        #pragma unroll
        for (int nt = 0; nt < 8; nt++) {
            float i0 = (s == 0) ? bse0[nt][0] : bse1[nt][0];
            float i1 = (s == 0) ? bse0[nt][1] : bse1[nt][1];
            h[nt][0] = i0; h[nt][1] = i1; h[nt][2] = i0; h[nt][3] = i1;
            #pragma unroll
            for (int kt = 0; kt < 2; kt++)
                mma_tf32(h[nt], xa[kt], w1f[nt][kt][0], w1f[nt][kt][1]);
        }

        // ---- tanh + divergence partials ----
        float d0 = 0.f, d1 = 0.f;   // rows g, g+8
        #pragma unroll
        for (int nt = 0; nt < 8; nt++) {
            h[nt][0] = fast_tanh(h[nt][0]);
            h[nt][1] = fast_tanh(h[nt][1]);
            h[nt][2] = fast_tanh(h[nt][2]);
            h[nt][3] = fast_tanh(h[nt][3]);
            d0 = fmaf(h[nt][0] * h[nt][0], cj[nt][0], d0);
            d0 = fmaf(h[nt][1] * h[nt][1], cj[nt][1], d0);
            d1 = fmaf(h[nt][2] * h[nt][2], cj[nt][0], d1);
            d1 = fmaf(h[nt][3] * h[nt][3], cj[nt][1], d1);
        }
        d0 += __shfl_xor_sync(0xffffffffu, d0, 1);
        d0 += __shfl_xor_sync(0xffffffffu, d0, 2);
        d1 += __shfl_xor_sync(0xffffffffu, d1, 1);
        d1 += __shfl_xor_sync(0xffffffffu, d1, 2);
        logq0 -= dt * (csum - d0);
        logq1 -= dt * (csum - d1);

        // ---- relayout h: C frags -> SMEM -> A frags ----
        #pragma unroll
        for (int nt = 0; nt < 8; nt++) {
            buf[g * BUFW       + 8 * nt + 2 * tg]     = h[nt][0];
            buf[g * BUFW       + 8 * nt + 2 * tg + 1] = h[nt][1];
            buf[(g + 8) * BUFW + 8 * nt + 2 * tg]     = h[nt][2];
            buf[(g + 8) * BUFW + 8 * nt + 2 * tg + 1] = h[nt][3];
        }
        __syncwarp();
        uint32_t ha[8][4];
        #pragma unroll
        for (int kt = 0; kt < 8; kt++) {
            ha[kt][0] = tf32(buf[g * BUFW       + 8 * kt + tg]);
            ha[kt][1] = tf32(buf[(g + 8) * BUFW + 8 * kt + tg]);
            ha[kt][2] = tf32(buf[g * BUFW       + 8 * kt + tg + 4]);
            ha[kt][3] = tf32(buf[(g + 8) * BUFW + 8 * kt + tg + 4]);
        }
        __syncwarp();

        // ---- GEMM2: v = h @ W2 + b2 ----
        float v[2][4];
        #pragma unroll
        for (int nt = 0; nt < 2; nt++) {
            v[nt][0] = b2f[nt][0]; v[nt][1] = b2f[nt][1];
            v[nt][2] = b2f[nt][0]; v[nt][3] = b2f[nt][1];
            #pragma unroll
            for (int kt = 0; kt < 8; kt++)
                mma_tf32(v[nt], ha[kt], w2f[kt][nt][0], w2f[kt][nt][1]);
        }

        // ---- relayout v (C frags -> SMEM -> x A-layout), exact fp32 update ----
        #pragma unroll
        for (int nt = 0; nt < 2; nt++) {
            buf[g * BUFW       + 8 * nt + 2 * tg]     = v[nt][0];
            buf[g * BUFW       + 8 * nt + 2 * tg + 1] = v[nt][1];
            buf[(g + 8) * BUFW + 8 * nt + 2 * tg]     = v[nt][2];
            buf[(g + 8) * BUFW + 8 * nt + 2 * tg + 1] = v[nt][3];
        }
        __syncwarp();
        #pragma unroll
        for (int kt = 0; kt < 2; kt++) {
            xe[kt][0] = fmaf(dt, buf[g * BUFW       + 8 * kt + tg],     xe[kt][0]);
            xe[kt][1] = fmaf(dt, buf[(g + 8) * BUFW + 8 * kt + tg],     xe[kt][1]);
            xe[kt][2] = fmaf(dt, buf[g * BUFW       + 8 * kt + tg + 4], xe[kt][2]);
            xe[kt][3] = fmaf(dt, buf[(g + 8) * BUFW + 8 * kt + tg + 4], xe[kt][3]);
        }
        __syncwarp();
    }

    // ---- output ----
    #pragma unroll
    for (int kt = 0; kt < 2; kt++) {
        out[(size_t)(row0 + g)     * 16 + 8 * kt + tg]     = xe[kt][0];
        out[(size_t)(row0 + g + 8) * 16 + 8 * kt + tg]     = xe[kt][1];
        out[(size_t)(row0 + g)     * 16 + 8 * kt + tg + 4] = xe[kt][2];
        out[(size_t)(row0 + g + 8) * 16 + 8 * kt + tg + 4] = xe[kt][3];
    }
    if (tg == 0) {
        out[(size_t)batch * 16 + row0 + g]     = logq0;
        out[(size_t)batch * 16 + row0 + g + 8] = logq1;
    }
}

extern "C" void kernel_launch(void* const* d_in, const int* in_sizes, int n_in,
                              void* d_out, int out_size) {
    const float* x0 = (const float*)d_in[0];
    const float* W1 = (const float*)d_in[1];
    const float* b1 = (const float*)d_in[2];
    const float* W2 = (const float*)d_in[3];
    const float* b2 = (const float*)d_in[4];
    float* out = (float*)d_out;

    const int batch = in_sizes[0] / 16;      // 131072, divisible by 64
    prep_kernel<<<1, 64>>>(W1, W2);
    const int blocks = batch / 64;           // 64 samples per 128-thread CTA
    flow_kernel<<<blocks, THREADS>>>(x0, W1, b1, W2, b2, out, batch);
}